// round 16
// baseline (speedup 1.0000x reference)
#include <cuda_runtime.h>

#define W 512
#define H 512
#define BATCH 2
#define HW (H*W)
#define NCV (BATCH*(H-1)*W)
#define NCH (BATCH*H*(W-1))
#define L_STEP 0.24f
#define KK 0.0009f   /* 0.03*0.03 */

#define TW 128
#define TH 64
#define HALO 12
#define TSX (TW - 2*HALO)   /* 104 interior width  */
#define TSY (TH - 2*HALO)   /* 40  interior height */
#define NBX 5               /* ceil(512/104) */
#define NBY 13              /* ceil(512/40)  */
#define NTI 32              /* lanes (x), 4 px each */
#define NTJ 16              /* warp-rows (y), 4 px each */
#define NTHREADS (NTI*NTJ)  /* 512 */
#define NCTAS (NBX*NBY*BATCH)   /* 130 <= 148 SMs: co-resident, sync safe */
#define NPH 42                  /* 41*12 + 8 = 500 steps */
#define FLAG_STRIDE 32          /* 128B apart: no same-line write serialization */

/* scratch state (ping-pong) + premultiplied conductances + sync flags */
__device__ float g_I0[BATCH*HW];
__device__ float g_I1[BATCH*HW];
__device__ float g_cvL[NCV];
__device__ float g_chL[NCH];
__device__ unsigned g_flags[NCTAS*FLAG_STRIDE];

/* ---- conductance kernels: raw g to d_out region, L*g to scratch ---- */
__global__ void k_coeff_v(const float* __restrict__ guide, float* __restrict__ out_cv) {
    int idx = blockIdx.x*blockDim.x + threadIdx.x;
    if (idx >= NCV) return;
    int x = idx % W;
    int y = (idx / W) % (H-1);
    int b = idx / (W*(H-1));
    const float* gb = guide + (size_t)b*3*HW + (size_t)y*W + x;
    float s = 0.f;
    #pragma unroll
    for (int c = 0; c < 3; c++) s += fabsf(gb[(size_t)c*HW + W] - gb[(size_t)c*HW]);
    float m = s * (1.0f/3.0f);
    float g = 1.0f / (1.0f + (m*m)/KK);
    out_cv[idx] = g;
    g_cvL[idx]  = L_STEP * g;
}

__global__ void k_coeff_h(const float* __restrict__ guide, float* __restrict__ out_ch) {
    int idx = blockIdx.x*blockDim.x + threadIdx.x;
    if (idx >= NCH) return;
    int x = idx % (W-1);
    int y = (idx / (W-1)) % H;
    int b = idx / ((W-1)*H);
    const float* gb = guide + (size_t)b*3*HW + (size_t)y*W + x;
    float s = 0.f;
    #pragma unroll
    for (int c = 0; c < 3; c++) s += fabsf(gb[(size_t)c*HW + 1] - gb[(size_t)c*HW]);
    float m = s * (1.0f/3.0f);
    float g = 1.0f / (1.0f + (m*m)/KK);
    out_ch[idx] = g;
    g_chL[idx]  = L_STEP * g;
}

__global__ void k_reset() {
    int idx = blockIdx.x*blockDim.x + threadIdx.x;
    if (idx < NCTAS) g_flags[idx*FLAG_STRIDE] = 0u;
}

__device__ __forceinline__ void flag_store_release(unsigned* p, unsigned v) {
    asm volatile("st.release.gpu.u32 [%0], %1;" :: "l"(p), "r"(v) : "memory");
}
__device__ __forceinline__ unsigned flag_load_acquire(const unsigned* p) {
    unsigned v;
    asm volatile("ld.acquire.gpu.u32 %0, [%1];" : "=r"(v) : "l"(p) : "memory");
    return v;
}

/* Neighbor-only inter-CTA sync (validated R14): release my flag, 8 threads
 * tight-spin on the 3x3 tile neighborhood's flags. Skew-1 safe with the
 * 2-buffer ping-pong; all 130 CTAs co-resident -> progress. */
__device__ __forceinline__ void neighbor_sync(int bx, int by, int b, int cta,
                                              unsigned target) {
    __syncthreads();
    if (threadIdx.x == 0) flag_store_release(&g_flags[cta*FLAG_STRIDE], target);
    if (threadIdx.x < 9 && threadIdx.x != 4) {
        int dx = (int)threadIdx.x % 3 - 1;
        int dy = (int)threadIdx.x / 3 - 1;
        int nx = bx + dx, ny = by + dy;
        if (nx >= 0 && nx < NBX && ny >= 0 && ny < NBY) {
            int nc = nx + NBX*(ny + NBY*b);
            while (flag_load_acquire(&g_flags[nc*FLAG_STRIDE]) < target) { }
        }
    }
    __syncthreads();
}

/* ---- persistent temporal-blocked diffusion, Jacobi form + trapezoidal
 * warp skipping ----
 * Jacobi single-pass update (validated R15):
 *   I' = cm*I + cv_r*up + cv_{r+1}*dn + ch_c*lf + ch_{c+1}*rt.
 * Trapezoid: at phase step s, garbage from an INTERIOR tile edge has depth
 * s (induction: result row r is garbage iff r <= s). Warp-row tj's rows
 * 4tj..4tj+3 are all garbage once s >= 4tj+3 (top) / s >= 63-4tj (bottom)
 * -> skip the whole step body (STS+shuffles+fp). Skipped warps still reach
 * __syncthreads (barrier outside the predicate). Stale smem from skipped
 * warps feeds only provably-garbage rows; edge warps take the reload path,
 * so the valid region is bit-identical to R15.
 * Every 12 steps: interior write, neighbor sync, reload (halo threads). */
__global__ void __launch_bounds__(NTHREADS, 1)
k_persist(const float* __restrict__ initial, float* __restrict__ out_y) {
    __shared__ float sTop[2][NTJ][TW];
    __shared__ float sBot[2][NTJ][TW];

    const int tid = threadIdx.x;
    const int ti  = tid & 31;
    const int tj  = tid >> 5;
    const int bx = blockIdx.x, by = blockIdx.y, b = blockIdx.z;
    const int cta = bx + NBX*(by + NBY*b);

    const int ox  = bx*TSX - HALO;
    const int oy  = by*TSY - HALO;
    const int lx0 = ti*4, ly0 = tj*4;
    const int gx0 = ox + lx0;
    const int gy0 = oy + ly0;
    const bool xok = (gx0 >= 0) && (gx0 + 4 <= W);
    const bool skipReload = (lx0 >= HALO) && (lx0 + 4 <= TW - HALO) &&
                            (ly0 >= HALO) && (ly0 + 4 <= TH - HALO);

    /* trapezoid skip thresholds: huge when that tile side is image boundary */
    const bool topInt = (oy >= 0);           /* top tile edge strictly inside */
    const bool botInt = (oy + TH < H);       /* bottom tile edge strictly inside */
    const int skipTopS = topInt ? (4*tj + 3)        : 1000;
    const int skipBotS = botInt ? (TH - 1 - 4*tj)   : 1000;
    const int skipS = (skipTopS < skipBotS) ? skipTopS : skipBotS;

    const float* __restrict__ cvb = g_cvL + (size_t)b*(H-1)*W;
    const float* __restrict__ chb = g_chL + (size_t)b*H*(W-1);

    /* persistent coefficients */
    float CV[5][4];
    #pragma unroll
    for (int jj = 0; jj < 5; jj++) {
        int r = gy0 - 1 + jj;
        if (xok && r >= 0 && r < H-1) {
            float4 v = *(const float4*)(cvb + (size_t)r*W + gx0);
            CV[jj][0]=v.x; CV[jj][1]=v.y; CV[jj][2]=v.z; CV[jj][3]=v.w;
        } else {
            CV[jj][0]=0.f; CV[jj][1]=0.f; CV[jj][2]=0.f; CV[jj][3]=0.f;
        }
    }
    float CH[4][5];
    #pragma unroll
    for (int j = 0; j < 4; j++) {
        int gy = gy0 + j;
        #pragma unroll
        for (int ii = 0; ii < 5; ii++) {
            int c = gx0 - 1 + ii;
            CH[j][ii] = (gy >= 0 && gy < H && c >= 0 && c < W-1)
                      ? chb[(size_t)gy*(W-1) + c] : 0.f;
        }
    }
    float CM[4][4];
    #pragma unroll
    for (int j = 0; j < 4; j++) {
        #pragma unroll
        for (int i = 0; i < 4; i++) {
            CM[j][i] = 1.0f - CV[j][i] - CV[j+1][i] - CH[j][i] - CH[j][i+1];
        }
    }

    float I[4][4];
    {
        const float* __restrict__ srcb = initial + (size_t)b*HW;
        #pragma unroll
        for (int j = 0; j < 4; j++) {
            int gy = gy0 + j;
            if (xok && gy >= 0 && gy < H) {
                float4 v = *(const float4*)(srcb + (size_t)gy*W + gx0);
                I[j][0]=v.x; I[j][1]=v.y; I[j][2]=v.z; I[j][3]=v.w;
            } else {
                I[j][0]=0.f; I[j][1]=0.f; I[j][2]=0.f; I[j][3]=0.f;
            }
        }
    }

    for (int p = 0; p < NPH; p++) {
        const int nsteps = (p == NPH-1) ? (500 - (NPH-1)*HALO) : HALO;
        #pragma unroll 2
        for (int s = 0; s < nsteps; s++) {
            const int bs = s & 1;
            const bool active = (s < skipS);

            float A[4][4];
            if (active) {
                /* publish boundary rows first (pre-update values) */
                *(float4*)&sTop[bs][tj][lx0] = make_float4(I[0][0],I[0][1],I[0][2],I[0][3]);
                *(float4*)&sBot[bs][tj][lx0] = make_float4(I[3][0],I[3][1],I[3][2],I[3][3]);

                float lf[4], rt[4];
                #pragma unroll
                for (int j = 0; j < 4; j++) {
                    lf[j] = __shfl_up_sync  (0xffffffffu, I[j][3], 1);
                    rt[j] = __shfl_down_sync(0xffffffffu, I[j][0], 1);
                }

                /* pre-barrier: horizontal+center + in-register vertical terms */
                #pragma unroll
                for (int j = 0; j < 4; j++) {
                    A[j][0] = fmaf(CH[j][1], I[j][1], fmaf(CH[j][0], lf[j],   CM[j][0]*I[j][0]));
                    A[j][1] = fmaf(CH[j][2], I[j][2], fmaf(CH[j][1], I[j][0], CM[j][1]*I[j][1]));
                    A[j][2] = fmaf(CH[j][3], I[j][3], fmaf(CH[j][2], I[j][1], CM[j][2]*I[j][2]));
                    A[j][3] = fmaf(CH[j][4], rt[j],   fmaf(CH[j][3], I[j][2], CM[j][3]*I[j][3]));
                }
                #pragma unroll
                for (int i = 0; i < 4; i++) {
                    A[1][i] = fmaf(CV[2][i], I[2][i], fmaf(CV[1][i], I[0][i], A[1][i]));
                    A[2][i] = fmaf(CV[3][i], I[3][i], fmaf(CV[2][i], I[1][i], A[2][i]));
                    A[0][i] = fmaf(CV[1][i], I[1][i], A[0][i]);
                    A[3][i] = fmaf(CV[3][i], I[2][i], A[3][i]);
                }
            }

            __syncthreads();   /* ALL warps, active or not */

            if (active) {
                float4 upv = (tj > 0)     ? *(float4*)&sBot[bs][tj-1][lx0] : make_float4(0,0,0,0);
                float4 dnv = (tj < NTJ-1) ? *(float4*)&sTop[bs][tj+1][lx0] : make_float4(0,0,0,0);
                float up[4] = {upv.x, upv.y, upv.z, upv.w};
                float dn[4] = {dnv.x, dnv.y, dnv.z, dnv.w};

                #pragma unroll
                for (int i = 0; i < 4; i++) {
                    I[0][i] = fmaf(CV[0][i], up[i], A[0][i]);
                    I[1][i] = A[1][i];
                    I[2][i] = A[2][i];
                    I[3][i] = fmaf(CV[4][i], dn[i], A[3][i]);
                }
            }
        }

        /* write interior: last phase straight to output, else ping-pong */
        float* __restrict__ wb = (p == NPH-1)
            ? (out_y + (size_t)b*HW)
            : (((p & 1) ? g_I0 : g_I1) + (size_t)b*HW);
        if (xok && lx0 >= HALO && lx0 < TW - HALO) {
            #pragma unroll
            for (int j = 0; j < 4; j++) {
                int ly = ly0 + j;
                int gy = gy0 + j;
                if (ly >= HALO && ly < TH - HALO && gy < H) {
                    *(float4*)(wb + (size_t)gy*W + gx0) =
                        make_float4(I[j][0], I[j][1], I[j][2], I[j][3]);
                }
            }
        }

        if (p < NPH-1) {
            neighbor_sync(bx, by, b, cta, (unsigned)(p + 1));
            if (!skipReload) {
                const float* __restrict__ rb = ((p & 1) ? g_I0 : g_I1) + (size_t)b*HW;
                #pragma unroll
                for (int j = 0; j < 4; j++) {
                    int gy = gy0 + j;
                    if (xok && gy >= 0 && gy < H) {
                        float4 v = *(const float4*)(rb + (size_t)gy*W + gx0);
                        I[j][0]=v.x; I[j][1]=v.y; I[j][2]=v.z; I[j][3]=v.w;
                    } else {
                        I[j][0]=0.f; I[j][1]=0.f; I[j][2]=0.f; I[j][3]=0.f;
                    }
                }
            }
        }
    }
}

extern "C" void kernel_launch(void* const* d_in, const int* in_sizes, int n_in,
                              void* d_out, int out_size) {
    const float* a0 = (const float*)d_in[0];
    const float* a1 = (const float*)d_in[1];
    const float* guide = a0;
    const float* initial = a1;
    if (n_in >= 2 && in_sizes[0] < in_sizes[1]) { guide = a1; initial = a0; }

    float* out    = (float*)d_out;
    float* out_y  = out;                       /* [BATCH*HW]   */
    float* out_cv = out + BATCH*HW;            /* [NCV]        */
    float* out_ch = out_cv + NCV;              /* [NCH]        */

    k_reset<<<1, 256>>>();
    k_coeff_v<<<(NCV + 255)/256, 256>>>(guide, out_cv);
    k_coeff_h<<<(NCH + 255)/256, 256>>>(guide, out_ch);

    dim3 grid(NBX, NBY, BATCH);
    k_persist<<<grid, NTHREADS>>>(initial, out_y);
}

// round 17
// speedup vs baseline: 1.2924x; 1.2924x over previous
#include <cuda_runtime.h>

#define W 512
#define H 512
#define BATCH 2
#define HW (H*W)
#define NCV (BATCH*(H-1)*W)
#define NCH (BATCH*H*(W-1))
#define L_STEP 0.24f
#define KK 0.0009f   /* 0.03*0.03 */

#define TW 128
#define TH 64
#define HALO 12
#define TSX (TW - 2*HALO)   /* 104 interior width  */
#define TSY (TH - 2*HALO)   /* 40  interior height */
#define NBX 5               /* ceil(512/104) */
#define NBY 13              /* ceil(512/40)  */
#define NTI 32              /* lanes (x), 4 px each */
#define NTJ 16              /* warp-rows (y), 4 px each */
#define NTHREADS (NTI*NTJ)  /* 512 */
#define NCTAS (NBX*NBY*BATCH)   /* 130 <= 148 SMs: co-resident, sync safe */
#define NPH 42                  /* 41*12 + 8 = 500 steps */
#define FLAG_STRIDE 32          /* 128B apart: no same-line write serialization */

/* scratch state (ping-pong) + premultiplied conductances + sync flags */
__device__ float g_I0[BATCH*HW];
__device__ float g_I1[BATCH*HW];
__device__ float g_cvL[NCV];
__device__ float g_chL[NCH];
__device__ unsigned g_flags[NCTAS*FLAG_STRIDE];

/* ---- conductance kernels: raw g to d_out region, L*g to scratch ---- */
__global__ void k_coeff_v(const float* __restrict__ guide, float* __restrict__ out_cv) {
    int idx = blockIdx.x*blockDim.x + threadIdx.x;
    if (idx >= NCV) return;
    int x = idx % W;
    int y = (idx / W) % (H-1);
    int b = idx / (W*(H-1));
    const float* gb = guide + (size_t)b*3*HW + (size_t)y*W + x;
    float s = 0.f;
    #pragma unroll
    for (int c = 0; c < 3; c++) s += fabsf(gb[(size_t)c*HW + W] - gb[(size_t)c*HW]);
    float m = s * (1.0f/3.0f);
    float g = 1.0f / (1.0f + (m*m)/KK);
    out_cv[idx] = g;
    g_cvL[idx]  = L_STEP * g;
}

__global__ void k_coeff_h(const float* __restrict__ guide, float* __restrict__ out_ch) {
    int idx = blockIdx.x*blockDim.x + threadIdx.x;
    if (idx >= NCH) return;
    int x = idx % (W-1);
    int y = (idx / (W-1)) % H;
    int b = idx / ((W-1)*H);
    const float* gb = guide + (size_t)b*3*HW + (size_t)y*W + x;
    float s = 0.f;
    #pragma unroll
    for (int c = 0; c < 3; c++) s += fabsf(gb[(size_t)c*HW + 1] - gb[(size_t)c*HW]);
    float m = s * (1.0f/3.0f);
    float g = 1.0f / (1.0f + (m*m)/KK);
    out_ch[idx] = g;
    g_chL[idx]  = L_STEP * g;
}

__global__ void k_reset() {
    int idx = blockIdx.x*blockDim.x + threadIdx.x;
    if (idx < NCTAS) g_flags[idx*FLAG_STRIDE] = 0u;
}

__device__ __forceinline__ void flag_store_release(unsigned* p, unsigned v) {
    asm volatile("st.release.gpu.u32 [%0], %1;" :: "l"(p), "r"(v) : "memory");
}
__device__ __forceinline__ unsigned flag_load_acquire(const unsigned* p) {
    unsigned v;
    asm volatile("ld.acquire.gpu.u32 %0, [%1];" : "=r"(v) : "l"(p) : "memory");
    return v;
}

/* Neighbor-only inter-CTA sync (validated R14): release my flag, 8 threads
 * tight-spin on the 3x3 tile neighborhood's flags. Skew-1 safe with the
 * 2-buffer ping-pong; all 130 CTAs co-resident -> progress. */
__device__ __forceinline__ void neighbor_sync(int bx, int by, int b, int cta,
                                              unsigned target) {
    __syncthreads();
    if (threadIdx.x == 0) flag_store_release(&g_flags[cta*FLAG_STRIDE], target);
    if (threadIdx.x < 9 && threadIdx.x != 4) {
        int dx = (int)threadIdx.x % 3 - 1;
        int dy = (int)threadIdx.x / 3 - 1;
        int nx = bx + dx, ny = by + dy;
        if (nx >= 0 && nx < NBX && ny >= 0 && ny < NBY) {
            int nc = nx + NBX*(ny + NBY*b);
            while (flag_load_acquire(&g_flags[nc*FLAG_STRIDE]) < target) { }
        }
    }
    __syncthreads();
}

/* ---- persistent temporal-blocked diffusion, Jacobi single-pass form ----
 * (validated R15 structure; step loop manually unrolled into even pairs
 * with literal buffer indices -- nsteps is always 12 or 8, both even.)
 *   I' = cm*I + cv_r*up + cv_{r+1}*dn + ch_c*lf + ch_{c+1}*rt,
 *   cm = 1 - cv_r - cv_{r+1} - ch_c - ch_{c+1}   (registers).
 * Rows 1,2 fully pre-barrier; rows 0,3 post-barrier = LDS -> 1 FFMA/px.
 * Every 12 steps: interior write, neighbor sync, reload (halo threads). */
__global__ void __launch_bounds__(NTHREADS, 1)
k_persist(const float* __restrict__ initial, float* __restrict__ out_y) {
    __shared__ float sTop[2][NTJ][TW];
    __shared__ float sBot[2][NTJ][TW];

    const int tid = threadIdx.x;
    const int ti  = tid & 31;
    const int tj  = tid >> 5;
    const int bx = blockIdx.x, by = blockIdx.y, b = blockIdx.z;
    const int cta = bx + NBX*(by + NBY*b);

    const int ox  = bx*TSX - HALO;
    const int oy  = by*TSY - HALO;
    const int lx0 = ti*4, ly0 = tj*4;
    const int gx0 = ox + lx0;
    const int gy0 = oy + ly0;
    const bool xok = (gx0 >= 0) && (gx0 + 4 <= W);
    const bool skipReload = (lx0 >= HALO) && (lx0 + 4 <= TW - HALO) &&
                            (ly0 >= HALO) && (ly0 + 4 <= TH - HALO);

    const float* __restrict__ cvb = g_cvL + (size_t)b*(H-1)*W;
    const float* __restrict__ chb = g_chL + (size_t)b*H*(W-1);

    /* persistent coefficients */
    float CV[5][4];   /* rows gy0-1 .. gy0+3 of L*cv */
    #pragma unroll
    for (int jj = 0; jj < 5; jj++) {
        int r = gy0 - 1 + jj;
        if (xok && r >= 0 && r < H-1) {
            float4 v = *(const float4*)(cvb + (size_t)r*W + gx0);
            CV[jj][0]=v.x; CV[jj][1]=v.y; CV[jj][2]=v.z; CV[jj][3]=v.w;
        } else {
            CV[jj][0]=0.f; CV[jj][1]=0.f; CV[jj][2]=0.f; CV[jj][3]=0.f;
        }
    }
    float CH[4][5];   /* cols gx0-1 .. gx0+3 of L*ch */
    #pragma unroll
    for (int j = 0; j < 4; j++) {
        int gy = gy0 + j;
        #pragma unroll
        for (int ii = 0; ii < 5; ii++) {
            int c = gx0 - 1 + ii;
            CH[j][ii] = (gy >= 0 && gy < H && c >= 0 && c < W-1)
                      ? chb[(size_t)gy*(W-1) + c] : 0.f;
        }
    }
    /* center weights: cm = 1 - cv_up - cv_dn - ch_lf - ch_rt */
    float CM[4][4];
    #pragma unroll
    for (int j = 0; j < 4; j++) {
        #pragma unroll
        for (int i = 0; i < 4; i++) {
            CM[j][i] = 1.0f - CV[j][i] - CV[j+1][i] - CH[j][i] - CH[j][i+1];
        }
    }

    /* initial state straight from input */
    float I[4][4];
    {
        const float* __restrict__ srcb = initial + (size_t)b*HW;
        #pragma unroll
        for (int j = 0; j < 4; j++) {
            int gy = gy0 + j;
            if (xok && gy >= 0 && gy < H) {
                float4 v = *(const float4*)(srcb + (size_t)gy*W + gx0);
                I[j][0]=v.x; I[j][1]=v.y; I[j][2]=v.z; I[j][3]=v.w;
            } else {
                I[j][0]=0.f; I[j][1]=0.f; I[j][2]=0.f; I[j][3]=0.f;
            }
        }
    }

    /* one diffusion step with a literal buffer index */
#define DIFF_STEP(BS)                                                          \
    do {                                                                       \
        *(float4*)&sTop[BS][tj][lx0] = make_float4(I[0][0],I[0][1],I[0][2],I[0][3]); \
        *(float4*)&sBot[BS][tj][lx0] = make_float4(I[3][0],I[3][1],I[3][2],I[3][3]); \
        float lf[4], rt[4];                                                    \
        _Pragma("unroll")                                                      \
        for (int j = 0; j < 4; j++) {                                          \
            lf[j] = __shfl_up_sync  (0xffffffffu, I[j][3], 1);                 \
            rt[j] = __shfl_down_sync(0xffffffffu, I[j][0], 1);                 \
        }                                                                      \
        float A[4][4];                                                         \
        _Pragma("unroll")                                                      \
        for (int j = 0; j < 4; j++) {                                          \
            A[j][0] = fmaf(CH[j][1], I[j][1], fmaf(CH[j][0], lf[j],   CM[j][0]*I[j][0])); \
            A[j][1] = fmaf(CH[j][2], I[j][2], fmaf(CH[j][1], I[j][0], CM[j][1]*I[j][1])); \
            A[j][2] = fmaf(CH[j][3], I[j][3], fmaf(CH[j][2], I[j][1], CM[j][2]*I[j][2])); \
            A[j][3] = fmaf(CH[j][4], rt[j],   fmaf(CH[j][3], I[j][2], CM[j][3]*I[j][3])); \
        }                                                                      \
        _Pragma("unroll")                                                      \
        for (int i = 0; i < 4; i++) {                                          \
            A[1][i] = fmaf(CV[2][i], I[2][i], fmaf(CV[1][i], I[0][i], A[1][i])); \
            A[2][i] = fmaf(CV[3][i], I[3][i], fmaf(CV[2][i], I[1][i], A[2][i])); \
            A[0][i] = fmaf(CV[1][i], I[1][i], A[0][i]);                        \
            A[3][i] = fmaf(CV[3][i], I[2][i], A[3][i]);                        \
        }                                                                      \
        __syncthreads();                                                       \
        float4 upv = (tj > 0)     ? *(float4*)&sBot[BS][tj-1][lx0] : make_float4(0,0,0,0); \
        float4 dnv = (tj < NTJ-1) ? *(float4*)&sTop[BS][tj+1][lx0] : make_float4(0,0,0,0); \
        float up[4] = {upv.x, upv.y, upv.z, upv.w};                            \
        float dn[4] = {dnv.x, dnv.y, dnv.z, dnv.w};                            \
        _Pragma("unroll")                                                      \
        for (int i = 0; i < 4; i++) {                                          \
            I[0][i] = fmaf(CV[0][i], up[i], A[0][i]);                          \
            I[1][i] = A[1][i];                                                 \
            I[2][i] = A[2][i];                                                 \
            I[3][i] = fmaf(CV[4][i], dn[i], A[3][i]);                          \
        }                                                                      \
    } while (0)

    for (int p = 0; p < NPH; p++) {
        const int npairs = (p == NPH-1) ? ((500 - (NPH-1)*HALO) / 2) : (HALO/2);
        for (int sp = 0; sp < npairs; sp++) {
            DIFF_STEP(0);
            DIFF_STEP(1);
        }

        /* write interior: last phase straight to output, else ping-pong */
        float* __restrict__ wb = (p == NPH-1)
            ? (out_y + (size_t)b*HW)
            : (((p & 1) ? g_I0 : g_I1) + (size_t)b*HW);
        if (xok && lx0 >= HALO && lx0 < TW - HALO) {
            #pragma unroll
            for (int j = 0; j < 4; j++) {
                int ly = ly0 + j;
                int gy = gy0 + j;
                if (ly >= HALO && ly < TH - HALO && gy < H) {
                    *(float4*)(wb + (size_t)gy*W + gx0) =
                        make_float4(I[j][0], I[j][1], I[j][2], I[j][3]);
                }
            }
        }

        if (p < NPH-1) {
            neighbor_sync(bx, by, b, cta, (unsigned)(p + 1));
            if (!skipReload) {
                const float* __restrict__ rb = ((p & 1) ? g_I0 : g_I1) + (size_t)b*HW;
                #pragma unroll
                for (int j = 0; j < 4; j++) {
                    int gy = gy0 + j;
                    if (xok && gy >= 0 && gy < H) {
                        float4 v = *(const float4*)(rb + (size_t)gy*W + gx0);
                        I[j][0]=v.x; I[j][1]=v.y; I[j][2]=v.z; I[j][3]=v.w;
                    } else {
                        I[j][0]=0.f; I[j][1]=0.f; I[j][2]=0.f; I[j][3]=0.f;
                    }
                }
            }
        }
    }
#undef DIFF_STEP
}

extern "C" void kernel_launch(void* const* d_in, const int* in_sizes, int n_in,
                              void* d_out, int out_size) {
    const float* a0 = (const float*)d_in[0];
    const float* a1 = (const float*)d_in[1];
    const float* guide = a0;
    const float* initial = a1;
    if (n_in >= 2 && in_sizes[0] < in_sizes[1]) { guide = a1; initial = a0; }

    float* out    = (float*)d_out;
    float* out_y  = out;                       /* [BATCH*HW]   */
    float* out_cv = out + BATCH*HW;            /* [NCV]        */
    float* out_ch = out_cv + NCV;              /* [NCH]        */

    k_reset<<<1, 256>>>();
    k_coeff_v<<<(NCV + 255)/256, 256>>>(guide, out_cv);
    k_coeff_h<<<(NCH + 255)/256, 256>>>(guide, out_ch);

    dim3 grid(NBX, NBY, BATCH);
    k_persist<<<grid, NTHREADS>>>(initial, out_y);
}